// round 17
// baseline (speedup 1.0000x reference)
#include <cuda_runtime.h>

// CenterLoss: loss = (1/B) * sum_i [ sxx/m^2 + scc - 2*sxc/m ],  m = max(sqrt(sxx),1e-12)
// B=16384, C=8192, D=64.
// R17 = R16 (benched 6.94us, cold 6.69 @ 910GB/s) with R=4 rows/half-warp to
// raise early MLP: 10 front-batched LDGs/thread (1 int4 label + 4 x.float4 +
// 4 centers.float4), 256 blocks all co-resident, 256 packed atomics.
// Finalize unchanged: ONE 64-bit atomicAdd carries sum (fixed-point, bits
// [0:54)) + arrival count (bits [54:64)); the return value gives the last
// block the complete prior sum -> plain-store publish + reset, no fence.
// (Valid: all terms are squared distances >= 0; total < 2^45 << 2^54.)

#define EPS 1e-12f
#define R 4   // rows per half-warp

#define CNT_ONE   (1ULL << 54)
#define SUM_MASK  (CNT_ONE - 1ULL)
#define FX_SCALE  4294967296.0   // 2^32

__device__ unsigned long long g_pack;   // zero at load; reset by last block each run

__global__ void __launch_bounds__(256)
center_loss_kernel(const float4* __restrict__ x,
                   const void* __restrict__ labels,
                   const float4* __restrict__ centers,
                   float* __restrict__ out,
                   float inv_batch)
{
    __shared__ float ssum[8];

    const int tid  = threadIdx.x;
    const int lane = tid & 31;
    const int wid  = tid >> 5;
    const int hw   = lane >> 4;         // half-warp id
    const int sub  = lane & 15;         // lane within half-warp
    const int base = (((blockIdx.x * 8 + wid) * 2) + hw) * R;  // first of R rows

    // ---- chain head: 4 labels in ONE LDG.128 (int32 view, safe for either
    // dtype: int64 labels in [0,8192) reinterpret as alternating {label,0},
    // all valid centers rows) ----
    int4 lquad = ((const int4*)labels)[base >> 2];

    // probe (bytes 4..255, in-bounds for any dtype) — resolved later, off-chain
    unsigned int probe = ((const unsigned int*)labels)[2 * lane + 1];

    // independent x loads fill the label-load shadow
    float4 xv[R];
    #pragma unroll
    for (int i = 0; i < R; ++i)
        xv[i] = x[(base + i) * 16 + sub];

    // ---- speculative gather straight off lquad (no ballot in the chain) ----
    int lab[R];
    lab[0] = lquad.x; lab[1] = lquad.y; lab[2] = lquad.z; lab[3] = lquad.w;
    float4 cv[R];
    #pragma unroll
    for (int i = 0; i < R; ++i)
        cv[i] = centers[lab[i] * 16 + sub];

    // dtype resolution overlaps the gather; int64 labels => all probes zero
    bool is32 = __ballot_sync(0xffffffffu, probe != 0u) != 0u;
    if (!is32) {  // int64 correction path (never taken for this dataset)
        #pragma unroll
        for (int i = 0; i < R; ++i) {
            lab[i] = (int)((const long long*)labels)[base + i];
            cv[i]  = centers[lab[i] * 16 + sub];
        }
    }

    // ---- per-row sums + half-warp (16-lane) reduction ----
    float local = 0.0f;
    #pragma unroll
    for (int i = 0; i < R; ++i) {
        float sxx = xv[i].x*xv[i].x + xv[i].y*xv[i].y + xv[i].z*xv[i].z + xv[i].w*xv[i].w;
        float sxc = xv[i].x*cv[i].x + xv[i].y*cv[i].y + xv[i].z*cv[i].z + xv[i].w*cv[i].w;
        float scc = cv[i].x*cv[i].x + cv[i].y*cv[i].y + cv[i].z*cv[i].z + cv[i].w*cv[i].w;
        #pragma unroll
        for (int o = 8; o; o >>= 1) {
            sxx += __shfl_xor_sync(0xffffffffu, sxx, o);
            sxc += __shfl_xor_sync(0xffffffffu, sxc, o);
            scc += __shfl_xor_sync(0xffffffffu, scc, o);
        }
        if (sub == 0) {
            // r = 1/max(sqrt(sxx), EPS) via MUFU.RSQ; guard keeps r finite.
            float r = rsqrtf(fmaxf(sxx, 1e-24f));
            local += sxx * r * r + scc - 2.0f * sxc * r;
        }
    }
    // fold the two half-warps into lane 0 of each warp
    local += __shfl_xor_sync(0xffffffffu, local, 16);

    // ---- block reduce: 8 warp partials -> ONE packed atomic ----
    if (lane == 0) ssum[wid] = local;
    __syncthreads();
    if (tid == 0) {
        float s = 0.0f;
        #pragma unroll
        for (int i = 0; i < 8; ++i) s += ssum[i];

        // partial >= 0 (sum of squared distances); pack as 2^32 fixed point.
        unsigned long long fx = (unsigned long long)((double)s * FX_SCALE);
        unsigned long long old = atomicAdd(&g_pack, CNT_ONE + fx);
        if ((old >> 54) == gridDim.x - 1u) {
            // Last arrival: prior sum is in the return value — no more atomics.
            unsigned long long total_fx = (old & SUM_MASK) + fx;
            *out = (float)((double)total_fx * (1.0 / FX_SCALE) * (double)inv_batch);
            g_pack = 0ULL;   // sole live writer; kernel-exit membar publishes
        }
    }
}

extern "C" void kernel_launch(void* const* d_in, const int* in_sizes, int n_in,
                              void* d_out, int out_size)
{
    const float4* x       = (const float4*)d_in[0];
    const void*   labels  = d_in[1];
    const float4* centers = (const float4*)d_in[2];
    float*        out     = (float*)d_out;

    const int batch = in_sizes[0] / 64;              // 16384
    const int rows_per_block = 8 * 2 * R;            // 64
    const int blocks = batch / rows_per_block;       // 256
    center_loss_kernel<<<blocks, 256>>>(x, labels, centers, out,
                                        1.0f / (float)batch);
}